// round 8
// baseline (speedup 1.0000x reference)
#include <cuda_runtime.h>
#include <cstdint>

// ===========================================================================
// SelfAttention via mma.sync tf32 — Round 8: operands pre-rounded to tf32
// once (weights prepass; qkv rounded in gemm1 epilogue; attn rounded in
// flash epilogue) so the hot mma loops carry ZERO cvt instructions.
// Bit-identical arithmetic to round 7 (cvt is idempotent).
//   K0: round w_qkv, w_out -> tf32 copies
//   K1: mma_gemm   x @ w_qkv_r           -> g_qkv  [16384 x 768] (tf32 bits)
//   K2: mma_flash  attention             -> g_attn [16384 x 256] (tf32 bits)
//   K1: mma_gemm   g_attn @ w_out_r + b  -> out    [16384 x 512]
// ===========================================================================

#define NTOK   16384
#define DMODEL 512
#define INNER  256
#define QKVN   768
#define HEADS  4
#define DH     64
#define TSEQ   2048

__device__ float g_qkv[NTOK * QKVN];      // 48 MB (tf32-rounded)
__device__ float g_attn[NTOK * INNER];    // 16 MB (tf32-rounded)
__device__ float g_wqkv_r[DMODEL * QKVN]; // 1.5 MB
__device__ float g_wout_r[INNER * DMODEL];// 0.5 MB

__device__ __forceinline__ uint32_t smem_u32(const void* p) {
    uint32_t a;
    asm("{ .reg .u64 t; cvta.to.shared.u64 t, %1; cvt.u32.u64 %0, t; }"
        : "=r"(a) : "l"(p));
    return a;
}
__device__ __forceinline__ uint32_t f2tf32(float x) {
    uint32_t r;
    asm("cvt.rna.tf32.f32 %0, %1;" : "=r"(r) : "f"(x));
    return r;
}
__device__ __forceinline__ uint32_t tf32_w(uint32_t bits) {
    return f2tf32(__uint_as_float(bits));
}
__device__ __forceinline__ void cp_async16(uint32_t saddr, const void* gptr) {
    asm volatile("cp.async.ca.shared.global [%0], [%1], 16;"
                 :: "r"(saddr), "l"(gptr));
}
#define CP_COMMIT() asm volatile("cp.async.commit_group;" ::: "memory")
#define CP_WAIT0()  asm volatile("cp.async.wait_group 0;" ::: "memory")

// D = A(16x8) @ B(8x8) + D, tf32 inputs, f32 accum
__device__ __forceinline__ void mma_tf32(float* c, const uint32_t* a,
                                         uint32_t b0, uint32_t b1) {
    asm volatile(
        "mma.sync.aligned.m16n8k8.row.col.f32.tf32.tf32.f32 "
        "{%0,%1,%2,%3}, {%4,%5,%6,%7}, {%8,%9}, {%0,%1,%2,%3};"
        : "+f"(c[0]), "+f"(c[1]), "+f"(c[2]), "+f"(c[3])
        : "r"(a[0]), "r"(a[1]), "r"(a[2]), "r"(a[3]), "r"(b0), "r"(b1));
}

// ------------------------- K0: tf32 rounding prepass ------------------------
__global__ void round_tf32_kernel(const float* __restrict__ src,
                                  float* __restrict__ dst, int n4) {
    int i = blockIdx.x * blockDim.x + threadIdx.x;
    if (i < n4) {
        float4 v = reinterpret_cast<const float4*>(src)[i];
        v.x = __uint_as_float(f2tf32(v.x));
        v.y = __uint_as_float(f2tf32(v.y));
        v.z = __uint_as_float(f2tf32(v.z));
        v.w = __uint_as_float(f2tf32(v.w));
        reinterpret_cast<float4*>(dst)[i] = v;
    }
}

// ---------------------------------------------------------------------------
// GEMM: C[M,N] = A[M,K] @ B[K,N] (+bias). 256 thr, CTA tile 256x128,
// kchunk 32, warp grid 4(m) x 2(n), warp tile 64x64. cp.async double buffer.
// CVTA: cvt A-fragments at load (only when A is a raw fp32 input).
// ROUND_OUT: round outputs to tf32 before store (feeding another mma kernel).
// AP=36 (==4 mod 32: A-frag banks 4g+tg). BP=136 (==8: B-frag banks 8tg+g).
// ---------------------------------------------------------------------------
#define AP 36
#define BP 136
#define GM_BS    (256 * AP)
#define GM_WORDS (GM_BS + 32 * BP)       // one buffer: 13568 words
#define GM_BYTES (2 * GM_WORDS * 4)      // 108544 B

template <bool CVTA, bool ROUND_OUT>
__global__ __launch_bounds__(256, 1) void mma_gemm_kernel(
    const float* __restrict__ A, const float* __restrict__ B,
    const float* __restrict__ bias, float* __restrict__ C,
    int M, int N, int K)
{
    extern __shared__ uint32_t sm[];
    const uint32_t smb = smem_u32(sm);

    const int tid = threadIdx.x;
    const int wid = tid >> 5, lane = tid & 31;
    const int g = lane >> 2, tg = lane & 3;
    const int wm = wid & 3, wn = wid >> 2;
    const int row0 = blockIdx.y * 256, col0 = blockIdx.x * 128;

    int ar[8], ac[8], br[4], bc[4];
    #pragma unroll
    for (int i = 0; i < 8; i++) {
        int flat = tid * 4 + i * 1024;
        ar[i] = flat >> 5; ac[i] = flat & 31;
    }
    #pragma unroll
    for (int i = 0; i < 4; i++) {
        int flat = tid * 4 + i * 1024;
        br[i] = flat >> 7; bc[i] = flat & 127;
    }

    float c[4][8][4];
    #pragma unroll
    for (int mt = 0; mt < 4; mt++)
        #pragma unroll
        for (int nt = 0; nt < 8; nt++)
            #pragma unroll
            for (int j = 0; j < 4; j++) c[mt][nt][j] = 0.f;

    const int nchunks = K >> 5;

    #pragma unroll
    for (int i = 0; i < 8; i++)
        cp_async16(smb + (ar[i] * AP + ac[i]) * 4,
                   A + (size_t)(row0 + ar[i]) * K + ac[i]);
    #pragma unroll
    for (int i = 0; i < 4; i++)
        cp_async16(smb + (GM_BS + br[i] * BP + bc[i]) * 4,
                   B + (size_t)br[i] * N + col0 + bc[i]);
    CP_COMMIT();
    CP_WAIT0();
    __syncthreads();

    for (int ch = 0; ch < nchunks; ch++) {
        const int cur = ch & 1;
        const uint32_t* As = sm + cur * GM_WORDS;
        const uint32_t* Bs = As + GM_BS;

        if (ch + 1 < nchunks) {
            const int nxt = cur ^ 1;
            const uint32_t nb = smb + nxt * GM_WORDS * 4;
            int k0 = (ch + 1) * 32;
            #pragma unroll
            for (int i = 0; i < 8; i++)
                cp_async16(nb + (ar[i] * AP + ac[i]) * 4,
                           A + (size_t)(row0 + ar[i]) * K + k0 + ac[i]);
            #pragma unroll
            for (int i = 0; i < 4; i++)
                cp_async16(nb + (GM_BS + br[i] * BP + bc[i]) * 4,
                           B + (size_t)(k0 + br[i]) * N + col0 + bc[i]);
            CP_COMMIT();
        }

        #pragma unroll
        for (int ks = 0; ks < 4; ks++) {
            uint32_t a[4][4], b[8][2];
            #pragma unroll
            for (int mt = 0; mt < 4; mt++) {
                int base = (wm * 64 + mt * 16) * AP + ks * 8;
                uint32_t w0 = As[base + g * AP + tg];
                uint32_t w1 = As[base + (g + 8) * AP + tg];
                uint32_t w2 = As[base + g * AP + tg + 4];
                uint32_t w3 = As[base + (g + 8) * AP + tg + 4];
                a[mt][0] = CVTA ? tf32_w(w0) : w0;
                a[mt][1] = CVTA ? tf32_w(w1) : w1;
                a[mt][2] = CVTA ? tf32_w(w2) : w2;
                a[mt][3] = CVTA ? tf32_w(w3) : w3;
            }
            #pragma unroll
            for (int nt = 0; nt < 8; nt++) {
                int bb = (ks * 8 + tg) * BP + wn * 64 + nt * 8 + g;
                b[nt][0] = Bs[bb];
                b[nt][1] = Bs[bb + 4 * BP];
            }
            #pragma unroll
            for (int mt = 0; mt < 4; mt++)
                #pragma unroll
                for (int nt = 0; nt < 8; nt++)
                    mma_tf32(c[mt][nt], a[mt], b[nt][0], b[nt][1]);
        }

        if (ch + 1 < nchunks) {
            CP_WAIT0();
            __syncthreads();
        }
    }

    #pragma unroll
    for (int mt = 0; mt < 4; mt++) {
        int r = row0 + wm * 64 + mt * 16 + g;
        #pragma unroll
        for (int nt = 0; nt < 8; nt++) {
            int cc = col0 + wn * 64 + nt * 8 + 2 * tg;
            float bx = 0.f, by = 0.f;
            if (bias) { bx = bias[cc]; by = bias[cc + 1]; }
            float e0 = c[mt][nt][0] + bx, e1 = c[mt][nt][1] + by;
            float e2 = c[mt][nt][2] + bx, e3 = c[mt][nt][3] + by;
            if (ROUND_OUT) {
                e0 = __uint_as_float(f2tf32(e0));
                e1 = __uint_as_float(f2tf32(e1));
                e2 = __uint_as_float(f2tf32(e2));
                e3 = __uint_as_float(f2tf32(e3));
            }
            *reinterpret_cast<float2*>(C + (size_t)r * N + cc) =
                make_float2(e0, e1);
            *reinterpret_cast<float2*>(C + (size_t)(r + 8) * N + cc) =
                make_float2(e2, e3);
        }
    }
}

// ---------------------------------------------------------------------------
// Flash attention. 256 thr / 8 warps. CTA: 256 q-rows of one (batch, head).
// Warp owns 32 q-rows = 2 mtiles, kv tiles of 64, K/V double-buffered via
// cp.async. qkv is pre-rounded tf32 -> NO cvt on Q/K/V paths (Q scale 0.125
// is an exact pow2). P still cvt'd at store. Output rounded for gemm2.
// Pitches: Qs/Ks/Ps 68 (==4 mod 32), Vs 72 (==8).
// ---------------------------------------------------------------------------
#define QP 68
#define VP 72
#define PP 68
#define FA_KS    (256 * QP)                      // Q: 256 x 68
#define FA_VS    (FA_KS + 2 * 64 * QP)           // K: 2 x 64 x 68
#define FA_PS    (FA_VS + 2 * 64 * VP)           // V: 2 x 64 x 72
#define FA_WORDS (FA_PS + 256 * PP)              // P: 256 x 68
#define FA_BYTES (FA_WORDS * 4)                  // 210944 B

__global__ __launch_bounds__(256, 1) void mma_flash_kernel(
    const float* __restrict__ qkv, float* __restrict__ attn)
{
    extern __shared__ uint32_t sm[];
    const uint32_t smb = smem_u32(sm);
    uint32_t* Qs = sm;
    uint32_t* Ps = sm + FA_PS;

    const int tid = threadIdx.x;
    const int wid = tid >> 5, lane = tid & 31;
    const int g = lane >> 2, tg = lane & 3;
    const int qt = blockIdx.x, h = blockIdx.y, bb = blockIdx.z;
    const int tok_q0 = bb * TSEQ + qt * 256;
    const int wb0 = wid * 32, wb1 = wid * 32 + 16;

    int kr[4], kc[4];
    #pragma unroll
    for (int i = 0; i < 4; i++) {
        int flat = tid * 4 + i * 1024;
        kr[i] = flat >> 6; kc[i] = flat & 63;
    }

    // preload kv-tile 0 into buffer 0
    {
        const int tok_k0 = bb * TSEQ;
        #pragma unroll
        for (int i = 0; i < 4; i++) {
            size_t gb = (size_t)(tok_k0 + kr[i]) * QKVN + h * DH + kc[i];
            cp_async16(smb + (FA_KS + kr[i] * QP + kc[i]) * 4, qkv + gb + INNER);
            cp_async16(smb + (FA_VS + kr[i] * VP + kc[i]) * 4, qkv + gb + 2 * INNER);
        }
        CP_COMMIT();
    }

    // Q tile 256x64, scaled by dh^-0.5 = 0.125 (exact on tf32 values; no cvt)
    #pragma unroll
    for (int i = 0; i < 16; i++) {
        int flat = tid * 4 + i * 1024;
        int r = flat >> 6, cc = flat & 63;
        float4 v = *reinterpret_cast<const float4*>(
            qkv + (size_t)(tok_q0 + r) * QKVN + h * DH + cc);
        Qs[r * QP + cc + 0] = __float_as_uint(v.x * 0.125f);
        Qs[r * QP + cc + 1] = __float_as_uint(v.y * 0.125f);
        Qs[r * QP + cc + 2] = __float_as_uint(v.z * 0.125f);
        Qs[r * QP + cc + 3] = __float_as_uint(v.w * 0.125f);
    }

    float m[2][2], l[2][2];
    #pragma unroll
    for (int mt = 0; mt < 2; mt++) {
        m[mt][0] = -1e30f; m[mt][1] = -1e30f;
        l[mt][0] = 0.f;    l[mt][1] = 0.f;
    }
    float o[2][8][4];
    #pragma unroll
    for (int mt = 0; mt < 2; mt++)
        #pragma unroll
        for (int nt = 0; nt < 8; nt++)
            #pragma unroll
            for (int j = 0; j < 4; j++) o[mt][nt][j] = 0.f;

    CP_WAIT0();
    __syncthreads();

    const int NT = TSEQ / 64;
    for (int kt = 0; kt < NT; kt++) {
        const int cur = kt & 1;
        const uint32_t* Ks = sm + FA_KS + cur * 64 * QP;
        const uint32_t* Vs = sm + FA_VS + cur * 64 * VP;

        if (kt + 1 < NT) {
            const int nxt = cur ^ 1;
            const int tok_k0 = bb * TSEQ + (kt + 1) * 64;
            #pragma unroll
            for (int i = 0; i < 4; i++) {
                size_t gb = (size_t)(tok_k0 + kr[i]) * QKVN + h * DH + kc[i];
                cp_async16(smb + (FA_KS + (nxt * 64 + kr[i]) * QP + kc[i]) * 4,
                           qkv + gb + INNER);
                cp_async16(smb + (FA_VS + (nxt * 64 + kr[i]) * VP + kc[i]) * 4,
                           qkv + gb + 2 * INNER);
            }
            CP_COMMIT();
        }

        // ---- S = Q @ K^T : both mtiles, shared K b-frags. 8 ntiles, 8 ks.
        float s0[8][4], s1[8][4];
        #pragma unroll
        for (int nt = 0; nt < 8; nt++)
            #pragma unroll
            for (int j = 0; j < 4; j++) { s0[nt][j] = 0.f; s1[nt][j] = 0.f; }
        #pragma unroll
        for (int ks = 0; ks < 8; ks++) {
            uint32_t a0[4], a1[4];
            int b0a = wb0 * QP + ks * 8, b1a = wb1 * QP + ks * 8;
            a0[0] = Qs[b0a + g * QP + tg];
            a0[1] = Qs[b0a + (g + 8) * QP + tg];
            a0[2] = Qs[b0a + g * QP + tg + 4];
            a0[3] = Qs[b0a + (g + 8) * QP + tg + 4];
            a1[0] = Qs[b1a + g * QP + tg];
            a1[1] = Qs[b1a + (g + 8) * QP + tg];
            a1[2] = Qs[b1a + g * QP + tg + 4];
            a1[3] = Qs[b1a + (g + 8) * QP + tg + 4];
            #pragma unroll
            for (int nt = 0; nt < 8; nt++) {
                int bidx = (nt * 8 + g) * QP + ks * 8 + tg;
                uint32_t kb0 = Ks[bidx];
                uint32_t kb1 = Ks[bidx + 4];
                mma_tf32(s0[nt], a0, kb0, kb1);
                mma_tf32(s1[nt], a1, kb0, kb1);
            }
        }

        // ---- online softmax per mtile
        #pragma unroll
        for (int mt = 0; mt < 2; mt++) {
            float (*s)[4] = mt ? s1 : s0;
            float mx0 = -1e30f, mx1 = -1e30f;
            #pragma unroll
            for (int nt = 0; nt < 8; nt++) {
                mx0 = fmaxf(mx0, fmaxf(s[nt][0], s[nt][1]));
                mx1 = fmaxf(mx1, fmaxf(s[nt][2], s[nt][3]));
            }
            mx0 = fmaxf(mx0, __shfl_xor_sync(0xffffffffu, mx0, 1));
            mx0 = fmaxf(mx0, __shfl_xor_sync(0xffffffffu, mx0, 2));
            mx1 = fmaxf(mx1, __shfl_xor_sync(0xffffffffu, mx1, 1));
            mx1 = fmaxf(mx1, __shfl_xor_sync(0xffffffffu, mx1, 2));
            const float mn0 = fmaxf(m[mt][0], mx0);
            const float mn1 = fmaxf(m[mt][1], mx1);
            const float al0 = __expf(m[mt][0] - mn0);
            const float al1 = __expf(m[mt][1] - mn1);
            float sum0 = 0.f, sum1 = 0.f;
            #pragma unroll
            for (int nt = 0; nt < 8; nt++) {
                s[nt][0] = __expf(s[nt][0] - mn0);
                s[nt][1] = __expf(s[nt][1] - mn0);
                s[nt][2] = __expf(s[nt][2] - mn1);
                s[nt][3] = __expf(s[nt][3] - mn1);
                sum0 += s[nt][0] + s[nt][1];
                sum1 += s[nt][2] + s[nt][3];
            }
            sum0 += __shfl_xor_sync(0xffffffffu, sum0, 1);
            sum0 += __shfl_xor_sync(0xffffffffu, sum0, 2);
            sum1 += __shfl_xor_sync(0xffffffffu, sum1, 1);
            sum1 += __shfl_xor_sync(0xffffffffu, sum1, 2);
            l[mt][0] = l[mt][0] * al0 + sum0; m[mt][0] = mn0;
            l[mt][1] = l[mt][1] * al1 + sum1; m[mt][1] = mn1;
            #pragma unroll
            for (int nt = 0; nt < 8; nt++) {
                o[mt][nt][0] *= al0; o[mt][nt][1] *= al0;
                o[mt][nt][2] *= al1; o[mt][nt][3] *= al1;
            }
            const int wb = mt ? wb1 : wb0;
            int r0 = (wb + g) * PP, r1 = (wb + g + 8) * PP;
            #pragma unroll
            for (int nt = 0; nt < 8; nt++) {
                int cc = nt * 8 + 2 * tg;
                Ps[r0 + cc]     = f2tf32(s[nt][0]);
                Ps[r0 + cc + 1] = f2tf32(s[nt][1]);
                Ps[r1 + cc]     = f2tf32(s[nt][2]);
                Ps[r1 + cc + 1] = f2tf32(s[nt][3]);
            }
        }
        __syncwarp();

        // ---- O += P @ V : shared V b-frags across both mtiles. 8 ks.
        #pragma unroll
        for (int ks = 0; ks < 8; ks++) {
            uint32_t a0[4], a1[4];
            int b0a = wb0 * PP + ks * 8, b1a = wb1 * PP + ks * 8;
            a0[0] = Ps[b0a + g * PP + tg];
            a0[1] = Ps[b0a + (g + 8) * PP + tg];
            a0[2] = Ps[b0a + g * PP + tg + 4];
            a0[3] = Ps[b0a + (g + 8) * PP + tg + 4];
            a1[0] = Ps[b1a + g * PP + tg];
            a1[1] = Ps[b1a + (g + 8) * PP + tg];
            a1[2] = Ps[b1a + g * PP + tg + 4];
            a1[3] = Ps[b1a + (g + 8) * PP + tg + 4];
            #pragma unroll
            for (int nt = 0; nt < 8; nt++) {
                int bidx = (ks * 8 + tg) * VP + nt * 8 + g;
                uint32_t vb0 = Vs[bidx];
                uint32_t vb1 = Vs[bidx + 4 * VP];
                mma_tf32(o[0][nt], a0, vb0, vb1);
                mma_tf32(o[1][nt], a1, vb0, vb1);
            }
        }
        __syncwarp();   // PV reads of Ps done before next-iter P stores

        if (kt + 1 < NT) {
            CP_WAIT0();
            __syncthreads();
        }
    }

    // epilogue: normalize and store tf32-rounded (gemm2 reads without cvt)
    #pragma unroll
    for (int mt = 0; mt < 2; mt++) {
        const float li0 = 1.f / l[mt][0], li1 = 1.f / l[mt][1];
        const int r = tok_q0 + wid * 32 + mt * 16 + g;
        #pragma unroll
        for (int nt = 0; nt < 8; nt++) {
            int cc = h * DH + nt * 8 + 2 * tg;
            float2 v0 = make_float2(
                __uint_as_float(f2tf32(o[mt][nt][0] * li0)),
                __uint_as_float(f2tf32(o[mt][nt][1] * li0)));
            float2 v1 = make_float2(
                __uint_as_float(f2tf32(o[mt][nt][2] * li1)),
                __uint_as_float(f2tf32(o[mt][nt][3] * li1)));
            *reinterpret_cast<float2*>(attn + (size_t)r * INNER + cc) = v0;
            *reinterpret_cast<float2*>(attn + (size_t)(r + 8) * INNER + cc) = v1;
        }
    }
}

// ---------------------------------------------------------------------------
extern "C" void kernel_launch(void* const* d_in, const int* in_sizes, int n_in,
                              void* d_out, int out_size)
{
    (void)in_sizes; (void)n_in; (void)out_size;
    const float* x     = (const float*)d_in[0];
    const float* w_qkv = (const float*)d_in[1];
    const float* w_out = (const float*)d_in[2];
    const float* b_out = (const float*)d_in[3];
    float* out = (float*)d_out;

    float *qkv_p, *attn_p, *wqkv_r, *wout_r;
    cudaGetSymbolAddress((void**)&qkv_p,  g_qkv);
    cudaGetSymbolAddress((void**)&attn_p, g_attn);
    cudaGetSymbolAddress((void**)&wqkv_r, g_wqkv_r);
    cudaGetSymbolAddress((void**)&wout_r, g_wout_r);

    cudaFuncSetAttribute(mma_gemm_kernel<true, true>,
        cudaFuncAttributeMaxDynamicSharedMemorySize, GM_BYTES);
    cudaFuncSetAttribute(mma_gemm_kernel<false, false>,
        cudaFuncAttributeMaxDynamicSharedMemorySize, GM_BYTES);
    cudaFuncSetAttribute(mma_flash_kernel,
        cudaFuncAttributeMaxDynamicSharedMemorySize, FA_BYTES);

    // K0: round weights to tf32 once
    round_tf32_kernel<<<(DMODEL * QKVN / 4 + 255) / 256, 256>>>(
        w_qkv, wqkv_r, DMODEL * QKVN / 4);
    round_tf32_kernel<<<(INNER * DMODEL / 4 + 255) / 256, 256>>>(
        w_out, wout_r, INNER * DMODEL / 4);

    // K1: QKV projection: [16384,512] @ [512,768], output tf32-rounded
    mma_gemm_kernel<true, true><<<dim3(QKVN / 128, NTOK / 256), 256, GM_BYTES>>>(
        x, wqkv_r, nullptr, qkv_p, NTOK, QKVN, DMODEL);
    // K2: attention (no cvt inside; output tf32-rounded)
    mma_flash_kernel<<<dim3(TSEQ / 256, HEADS, 8), 256, FA_BYTES>>>(
        qkv_p, attn_p);
    // K1: output projection: [16384,256] @ [256,512] + bias (no cvt)
    mma_gemm_kernel<false, false><<<dim3(DMODEL / 128, NTOK / 256), 256, GM_BYTES>>>(
        attn_p, wout_r, b_out, out, NTOK, DMODEL, INNER);
}

// round 10
// speedup vs baseline: 1.5059x; 1.5059x over previous
#include <cuda_runtime.h>
#include <cstdint>

// ===========================================================================
// SelfAttention via mma.sync tf32 — Round 9: revert R8; flash reshaped to
// 128-thr CTAs (4 warps, 128 q-rows, single-buffer K/V) so 2 CTAs/SM fit
// -> 4 warps/SMSP for issue-bound mma stream. GEMM = round-7 cp.async best.
//   K1: mma_gemm   x @ w_qkv            -> g_qkv  [16384 x 768]
//   K2: mma_flash  attention            -> g_attn [16384 x 256]
//   K1: mma_gemm   g_attn @ w_out + b   -> out    [16384 x 512]
// ===========================================================================

#define NTOK   16384
#define DMODEL 512
#define INNER  256
#define QKVN   768
#define HEADS  4
#define DH     64
#define TSEQ   2048

__device__ float g_qkv[NTOK * QKVN];    // 48 MB
__device__ float g_attn[NTOK * INNER];  // 16 MB

__device__ __forceinline__ uint32_t smem_u32(const void* p) {
    uint32_t a;
    asm("{ .reg .u64 t; cvta.to.shared.u64 t, %1; cvt.u32.u64 %0, t; }"
        : "=r"(a) : "l"(p));
    return a;
}
__device__ __forceinline__ uint32_t f2tf32(float x) {
    uint32_t r;
    asm("cvt.rna.tf32.f32 %0, %1;" : "=r"(r) : "f"(x));
    return r;
}
__device__ __forceinline__ uint32_t tf32_w(uint32_t bits) {
    return f2tf32(__uint_as_float(bits));
}
__device__ __forceinline__ void cp_async16(uint32_t saddr, const void* gptr) {
    asm volatile("cp.async.ca.shared.global [%0], [%1], 16;"
                 :: "r"(saddr), "l"(gptr));
}
#define CP_COMMIT() asm volatile("cp.async.commit_group;" ::: "memory")
#define CP_WAIT0()  asm volatile("cp.async.wait_group 0;" ::: "memory")

// D = A(16x8) @ B(8x8) + D, tf32 inputs, f32 accum
__device__ __forceinline__ void mma_tf32(float* c, const uint32_t* a,
                                         uint32_t b0, uint32_t b1) {
    asm volatile(
        "mma.sync.aligned.m16n8k8.row.col.f32.tf32.tf32.f32 "
        "{%0,%1,%2,%3}, {%4,%5,%6,%7}, {%8,%9}, {%0,%1,%2,%3};"
        : "+f"(c[0]), "+f"(c[1]), "+f"(c[2]), "+f"(c[3])
        : "r"(a[0]), "r"(a[1]), "r"(a[2]), "r"(a[3]), "r"(b0), "r"(b1));
}

// ---------------------------------------------------------------------------
// GEMM (round-7 best): C = A @ B (+bias). 256 thr, CTA tile 256x128,
// kchunk 32, warp tile 64x64, cp.async double buffer, cvt at fragment load.
// AP=36 (==4 mod 32), BP=136 (==8 mod 32): conflict-free fragments.
// ---------------------------------------------------------------------------
#define AP 36
#define BP 136
#define GM_BS    (256 * AP)
#define GM_WORDS (GM_BS + 32 * BP)       // one buffer: 13568 words
#define GM_BYTES (2 * GM_WORDS * 4)      // 108544 B

__global__ __launch_bounds__(256, 1) void mma_gemm_kernel(
    const float* __restrict__ A, const float* __restrict__ B,
    const float* __restrict__ bias, float* __restrict__ C,
    int M, int N, int K)
{
    extern __shared__ uint32_t sm[];
    const uint32_t smb = smem_u32(sm);

    const int tid = threadIdx.x;
    const int wid = tid >> 5, lane = tid & 31;
    const int g = lane >> 2, tg = lane & 3;
    const int wm = wid & 3, wn = wid >> 2;
    const int row0 = blockIdx.y * 256, col0 = blockIdx.x * 128;

    int ar[8], ac[8], br[4], bc[4];
    #pragma unroll
    for (int i = 0; i < 8; i++) {
        int flat = tid * 4 + i * 1024;
        ar[i] = flat >> 5; ac[i] = flat & 31;
    }
    #pragma unroll
    for (int i = 0; i < 4; i++) {
        int flat = tid * 4 + i * 1024;
        br[i] = flat >> 7; bc[i] = flat & 127;
    }

    float c[4][8][4];
    #pragma unroll
    for (int mt = 0; mt < 4; mt++)
        #pragma unroll
        for (int nt = 0; nt < 8; nt++)
            #pragma unroll
            for (int j = 0; j < 4; j++) c[mt][nt][j] = 0.f;

    const int nchunks = K >> 5;

    #pragma unroll
    for (int i = 0; i < 8; i++)
        cp_async16(smb + (ar[i] * AP + ac[i]) * 4,
                   A + (size_t)(row0 + ar[i]) * K + ac[i]);
    #pragma unroll
    for (int i = 0; i < 4; i++)
        cp_async16(smb + (GM_BS + br[i] * BP + bc[i]) * 4,
                   B + (size_t)br[i] * N + col0 + bc[i]);
    CP_COMMIT();
    CP_WAIT0();
    __syncthreads();

    for (int ch = 0; ch < nchunks; ch++) {
        const int cur = ch & 1;
        const uint32_t* As = sm + cur * GM_WORDS;
        const uint32_t* Bs = As + GM_BS;

        if (ch + 1 < nchunks) {
            const int nxt = cur ^ 1;
            const uint32_t nb = smb + nxt * GM_WORDS * 4;
            int k0 = (ch + 1) * 32;
            #pragma unroll
            for (int i = 0; i < 8; i++)
                cp_async16(nb + (ar[i] * AP + ac[i]) * 4,
                           A + (size_t)(row0 + ar[i]) * K + k0 + ac[i]);
            #pragma unroll
            for (int i = 0; i < 4; i++)
                cp_async16(nb + (GM_BS + br[i] * BP + bc[i]) * 4,
                           B + (size_t)(k0 + br[i]) * N + col0 + bc[i]);
            CP_COMMIT();
        }

        #pragma unroll
        for (int ks = 0; ks < 4; ks++) {
            uint32_t a[4][4], b[8][2];
            #pragma unroll
            for (int mt = 0; mt < 4; mt++) {
                int base = (wm * 64 + mt * 16) * AP + ks * 8;
                a[mt][0] = tf32_w(As[base + g * AP + tg]);
                a[mt][1] = tf32_w(As[base + (g + 8) * AP + tg]);
                a[mt][2] = tf32_w(As[base + g * AP + tg + 4]);
                a[mt][3] = tf32_w(As[base + (g + 8) * AP + tg + 4]);
            }
            #pragma unroll
            for (int nt = 0; nt < 8; nt++) {
                int bb = (ks * 8 + tg) * BP + wn * 64 + nt * 8 + g;
                b[nt][0] = tf32_w(Bs[bb]);
                b[nt][1] = tf32_w(Bs[bb + 4 * BP]);
            }
            #pragma unroll
            for (int mt = 0; mt < 4; mt++)
                #pragma unroll
                for (int nt = 0; nt < 8; nt++)
                    mma_tf32(c[mt][nt], a[mt], b[nt][0], b[nt][1]);
        }

        if (ch + 1 < nchunks) {
            CP_WAIT0();
            __syncthreads();
        }
    }

    #pragma unroll
    for (int mt = 0; mt < 4; mt++) {
        int r = row0 + wm * 64 + mt * 16 + g;
        #pragma unroll
        for (int nt = 0; nt < 8; nt++) {
            int cc = col0 + wn * 64 + nt * 8 + 2 * tg;
            float bx = 0.f, by = 0.f;
            if (bias) { bx = bias[cc]; by = bias[cc + 1]; }
            float2 v0 = make_float2(c[mt][nt][0] + bx, c[mt][nt][1] + by);
            float2 v1 = make_float2(c[mt][nt][2] + bx, c[mt][nt][3] + by);
            *reinterpret_cast<float2*>(C + (size_t)r * N + cc) = v0;
            *reinterpret_cast<float2*>(C + (size_t)(r + 8) * N + cc) = v1;
        }
    }
}

// ---------------------------------------------------------------------------
// Flash attention (round-6 arithmetic, reshaped for occupancy 2):
// 128 thr / 4 warps per CTA; CTA covers 128 q-rows of one (batch, head).
// Warp owns 32 q-rows = 2 mtiles; kv tiles of 64, single buffer (co-resident
// CTA hides load latency). K and V b-frags shared across both mtiles.
// Pitches: Qs/Ks/Ps 68 (==4 mod 32), Vs 72 (==8). smem = 105472 B -> 2/SM.
// ---------------------------------------------------------------------------
#define QP 68
#define VP 72
#define PP 68
#define FA_KS    (128 * QP)                      // Q: 128 x 68
#define FA_VS    (FA_KS + 64 * QP)               // K: 64 x 68
#define FA_PS    (FA_VS + 64 * VP)               // V: 64 x 72
#define FA_WORDS (FA_PS + 128 * PP)              // P: 128 x 68
#define FA_BYTES (FA_WORDS * 4)                  // 105472 B

__global__ __launch_bounds__(128, 2) void mma_flash_kernel(
    const float* __restrict__ qkv, float* __restrict__ attn)
{
    extern __shared__ uint32_t sm[];
    uint32_t* Qs = sm;
    uint32_t* Ks = sm + FA_KS;
    uint32_t* Vs = sm + FA_VS;
    uint32_t* Ps = sm + FA_PS;

    const int tid = threadIdx.x;
    const int wid = tid >> 5, lane = tid & 31;
    const int g = lane >> 2, tg = lane & 3;
    const int qt = blockIdx.x, h = blockIdx.y, bb = blockIdx.z;
    const int tok_q0 = bb * TSEQ + qt * 128;
    const int wb0 = wid * 32, wb1 = wid * 32 + 16;

    // Q tile 128x64 (pre-scaled by dh^-0.5 = 0.125), cvt at store
    #pragma unroll
    for (int i = 0; i < 16; i++) {
        int flat = tid * 4 + i * 512;
        int r = flat >> 6, cc = flat & 63;
        float4 v = *reinterpret_cast<const float4*>(
            qkv + (size_t)(tok_q0 + r) * QKVN + h * DH + cc);
        Qs[r * QP + cc + 0] = f2tf32(v.x * 0.125f);
        Qs[r * QP + cc + 1] = f2tf32(v.y * 0.125f);
        Qs[r * QP + cc + 2] = f2tf32(v.z * 0.125f);
        Qs[r * QP + cc + 3] = f2tf32(v.w * 0.125f);
    }

    float m[2][2], l[2][2];
    #pragma unroll
    for (int mt = 0; mt < 2; mt++) {
        m[mt][0] = -1e30f; m[mt][1] = -1e30f;
        l[mt][0] = 0.f;    l[mt][1] = 0.f;
    }
    float o[2][8][4];
    #pragma unroll
    for (int mt = 0; mt < 2; mt++)
        #pragma unroll
        for (int nt = 0; nt < 8; nt++)
            #pragma unroll
            for (int j = 0; j < 4; j++) o[mt][nt][j] = 0.f;

    for (int kt = 0; kt < TSEQ / 64; kt++) {
        const int tok_k0 = bb * TSEQ + kt * 64;
        __syncthreads();   // prior iter done reading Ks/Vs (Q stores, kt=0)
        #pragma unroll
        for (int i = 0; i < 8; i++) {     // K/V tiles 64x64 each
            int flat = tid * 4 + i * 512;
            int r = flat >> 6, cc = flat & 63;
            size_t base = (size_t)(tok_k0 + r) * QKVN + h * DH + cc;
            float4 kv4 = *reinterpret_cast<const float4*>(qkv + base + INNER);
            float4 vv4 = *reinterpret_cast<const float4*>(qkv + base + 2 * INNER);
            Ks[r * QP + cc + 0] = f2tf32(kv4.x);
            Ks[r * QP + cc + 1] = f2tf32(kv4.y);
            Ks[r * QP + cc + 2] = f2tf32(kv4.z);
            Ks[r * QP + cc + 3] = f2tf32(kv4.w);
            Vs[r * VP + cc + 0] = f2tf32(vv4.x);
            Vs[r * VP + cc + 1] = f2tf32(vv4.y);
            Vs[r * VP + cc + 2] = f2tf32(vv4.z);
            Vs[r * VP + cc + 3] = f2tf32(vv4.w);
        }
        __syncthreads();

        // ---- S = Q @ K^T : both mtiles, shared K b-frags. 8 ntiles, 8 ks.
        float s0[8][4], s1[8][4];
        #pragma unroll
        for (int nt = 0; nt < 8; nt++)
            #pragma unroll
            for (int j = 0; j < 4; j++) { s0[nt][j] = 0.f; s1[nt][j] = 0.f; }
        #pragma unroll
        for (int ks = 0; ks < 8; ks++) {
            uint32_t a0[4], a1[4];
            int b0a = wb0 * QP + ks * 8, b1a = wb1 * QP + ks * 8;
            a0[0] = Qs[b0a + g * QP + tg];
            a0[1] = Qs[b0a + (g + 8) * QP + tg];
            a0[2] = Qs[b0a + g * QP + tg + 4];
            a0[3] = Qs[b0a + (g + 8) * QP + tg + 4];
            a1[0] = Qs[b1a + g * QP + tg];
            a1[1] = Qs[b1a + (g + 8) * QP + tg];
            a1[2] = Qs[b1a + g * QP + tg + 4];
            a1[3] = Qs[b1a + (g + 8) * QP + tg + 4];
            #pragma unroll
            for (int nt = 0; nt < 8; nt++) {
                int bidx = (nt * 8 + g) * QP + ks * 8 + tg;
                uint32_t kb0 = Ks[bidx], kb1 = Ks[bidx + 4];
                mma_tf32(s0[nt], a0, kb0, kb1);
                mma_tf32(s1[nt], a1, kb0, kb1);
            }
        }

        // ---- online softmax per mtile
        #pragma unroll
        for (int mt = 0; mt < 2; mt++) {
            float (*s)[4] = mt ? s1 : s0;
            float mx0 = -1e30f, mx1 = -1e30f;
            #pragma unroll
            for (int nt = 0; nt < 8; nt++) {
                mx0 = fmaxf(mx0, fmaxf(s[nt][0], s[nt][1]));
                mx1 = fmaxf(mx1, fmaxf(s[nt][2], s[nt][3]));
            }
            mx0 = fmaxf(mx0, __shfl_xor_sync(0xffffffffu, mx0, 1));
            mx0 = fmaxf(mx0, __shfl_xor_sync(0xffffffffu, mx0, 2));
            mx1 = fmaxf(mx1, __shfl_xor_sync(0xffffffffu, mx1, 1));
            mx1 = fmaxf(mx1, __shfl_xor_sync(0xffffffffu, mx1, 2));
            const float mn0 = fmaxf(m[mt][0], mx0);
            const float mn1 = fmaxf(m[mt][1], mx1);
            const float al0 = __expf(m[mt][0] - mn0);
            const float al1 = __expf(m[mt][1] - mn1);
            float sum0 = 0.f, sum1 = 0.f;
            #pragma unroll
            for (int nt = 0; nt < 8; nt++) {
                s[nt][0] = __expf(s[nt][0] - mn0);
                s[nt][1] = __expf(s[nt][1] - mn0);
                s[nt][2] = __expf(s[nt][2] - mn1);
                s[nt][3] = __expf(s[nt][3] - mn1);
                sum0 += s[nt][0] + s[nt][1];
                sum1 += s[nt][2] + s[nt][3];
            }
            sum0 += __shfl_xor_sync(0xffffffffu, sum0, 1);
            sum0 += __shfl_xor_sync(0xffffffffu, sum0, 2);
            sum1 += __shfl_xor_sync(0xffffffffu, sum1, 1);
            sum1 += __shfl_xor_sync(0xffffffffu, sum1, 2);
            l[mt][0] = l[mt][0] * al0 + sum0; m[mt][0] = mn0;
            l[mt][1] = l[mt][1] * al1 + sum1; m[mt][1] = mn1;
            #pragma unroll
            for (int nt = 0; nt < 8; nt++) {
                o[mt][nt][0] *= al0; o[mt][nt][1] *= al0;
                o[mt][nt][2] *= al1; o[mt][nt][3] *= al1;
            }
            // P -> SMEM (warp-private rows)
            const int wb = mt ? wb1 : wb0;
            int r0 = (wb + g) * PP, r1 = (wb + g + 8) * PP;
            #pragma unroll
            for (int nt = 0; nt < 8; nt++) {
                int cc = nt * 8 + 2 * tg;
                Ps[r0 + cc]     = f2tf32(s[nt][0]);
                Ps[r0 + cc + 1] = f2tf32(s[nt][1]);
                Ps[r1 + cc]     = f2tf32(s[nt][2]);
                Ps[r1 + cc + 1] = f2tf32(s[nt][3]);
            }
        }
        __syncwarp();

        // ---- O += P @ V : shared V b-frags across both mtiles. 8 ks.
        #pragma unroll
        for (int ks = 0; ks < 8; ks++) {
            uint32_t a0[4], a1[4];
            int b0a = wb0 * PP + ks * 8, b1a = wb1 * PP + ks * 8;
            a0[0] = Ps[b0a + g * PP + tg];
            a0[1] = Ps[b0a + (g + 8) * PP + tg];
            a0[2] = Ps[b0a + g * PP + tg + 4];
            a0[3] = Ps[b0a + (g + 8) * PP + tg + 4];
            a1[0] = Ps[b1a + g * PP + tg];
            a1[1] = Ps[b1a + (g + 8) * PP + tg];
            a1[2] = Ps[b1a + g * PP + tg + 4];
            a1[3] = Ps[b1a + (g + 8) * PP + tg + 4];
            #pragma unroll
            for (int nt = 0; nt < 8; nt++) {
                int bidx = (ks * 8 + tg) * VP + nt * 8 + g;
                uint32_t vb0 = Vs[bidx], vb1 = Vs[bidx + 4 * VP];
                mma_tf32(o[0][nt], a0, vb0, vb1);
                mma_tf32(o[1][nt], a1, vb0, vb1);
            }
        }
        __syncwarp();   // PV reads of Ps done before next-iter P stores
    }

    #pragma unroll
    for (int mt = 0; mt < 2; mt++) {
        const float li0 = 1.f / l[mt][0], li1 = 1.f / l[mt][1];
        const int r = tok_q0 + wid * 32 + mt * 16 + g;
        #pragma unroll
        for (int nt = 0; nt < 8; nt++) {
            int cc = h * DH + nt * 8 + 2 * tg;
            float2 v0 = make_float2(o[mt][nt][0] * li0, o[mt][nt][1] * li0);
            float2 v1 = make_float2(o[mt][nt][2] * li1, o[mt][nt][3] * li1);
            *reinterpret_cast<float2*>(attn + (size_t)r * INNER + cc) = v0;
            *reinterpret_cast<float2*>(attn + (size_t)(r + 8) * INNER + cc) = v1;
        }
    }
}

// ---------------------------------------------------------------------------
extern "C" void kernel_launch(void* const* d_in, const int* in_sizes, int n_in,
                              void* d_out, int out_size)
{
    (void)in_sizes; (void)n_in; (void)out_size;
    const float* x     = (const float*)d_in[0];
    const float* w_qkv = (const float*)d_in[1];
    const float* w_out = (const float*)d_in[2];
    const float* b_out = (const float*)d_in[3];
    float* out = (float*)d_out;

    float *qkv_p, *attn_p;
    cudaGetSymbolAddress((void**)&qkv_p,  g_qkv);
    cudaGetSymbolAddress((void**)&attn_p, g_attn);

    cudaFuncSetAttribute(mma_gemm_kernel,
        cudaFuncAttributeMaxDynamicSharedMemorySize, GM_BYTES);
    cudaFuncSetAttribute(mma_flash_kernel,
        cudaFuncAttributeMaxDynamicSharedMemorySize, FA_BYTES);

    // QKV projection: [16384,512] @ [512,768]
    mma_gemm_kernel<<<dim3(QKVN / 128, NTOK / 256), 256, GM_BYTES>>>(
        x, w_qkv, nullptr, qkv_p, NTOK, QKVN, DMODEL);
    // attention: 128 q-rows per CTA, 2 CTAs/SM
    mma_flash_kernel<<<dim3(TSEQ / 128, HEADS, 8), 128, FA_BYTES>>>(
        qkv_p, attn_p);
    // output projection: [16384,256] @ [256,512] + bias
    mma_gemm_kernel<<<dim3(DMODEL / 128, NTOK / 256), 256, GM_BYTES>>>(
        attn_p, w_out, b_out, out, NTOK, DMODEL, INNER);
}